// round 8
// baseline (speedup 1.0000x reference)
#include <cuda_runtime.h>
#include <cuda_fp16.h>
#include <math.h>
#include <stdint.h>

#define BB 16
#define CC 384
#define HH 64
#define WW 64
#define NT (BB*HH*WW)   // 65536 tokens

// ---------------- scratch (static device globals; no allocs) ----------------
__device__ float  g_M [NT*CC];    // modulation (gemm2 out)
__device__ float  g_X1[NT*CC];    // xs (gemm1 out), then dctw out
__device__ float  g_A [NT*CC];    // DCT-H out
__device__ __half g_H1[NT*CC];    // conv out (gemm1 A), later ln out (gemm3 A)
__device__ __half g_H2[NT*CC];    // freq half (gemm2 A)
__device__ __half g_Hz[NT*CC];    // z (fp16, gemm1 out cols 384..767)
__device__ __half g_WH[768*384 + 2*384*384];  // half weights
__device__ float  g_WbfT[32*64];  // [h][p*32+j] = W[2j+p][h], h<32
__device__ float  g_WbfJ[2*32*32];// [p][j][h]   = W[2j+p][h]
__device__ float  g_ldec[64*64];  // -(wn^2+wm^2) at (n,m)

// ---------------- helpers ----------------
__device__ __forceinline__ void cpa16(void* smem, const void* gmem) {
    unsigned s = (unsigned)__cvta_generic_to_shared(smem);
    asm volatile("cp.async.cg.shared.global [%0], [%1], 16;\n" :: "r"(s), "l"(gmem));
}

__device__ __forceinline__ void mma_fp16(float* d, const uint32_t* a, const uint32_t* b) {
    asm volatile(
        "mma.sync.aligned.m16n8k16.row.col.f32.f16.f16.f32 "
        "{%0,%1,%2,%3}, {%4,%5,%6,%7}, {%8,%9}, {%0,%1,%2,%3};\n"
        : "+f"(d[0]), "+f"(d[1]), "+f"(d[2]), "+f"(d[3])
        : "r"(a[0]), "r"(a[1]), "r"(a[2]), "r"(a[3]), "r"(b[0]), "r"(b[1]));
}

__device__ __forceinline__ void ldsm_x4(uint32_t& r0, uint32_t& r1, uint32_t& r2, uint32_t& r3,
                                        uint32_t addr) {
    asm volatile("ldmatrix.sync.aligned.m8n8.x4.shared.b16 {%0,%1,%2,%3}, [%4];"
                 : "=r"(r0), "=r"(r1), "=r"(r2), "=r"(r3) : "r"(addr));
}

// ---------------- init: packed butterfly DCT basis + decay log ----------------
__global__ void init_kernel() {
    int idx = blockIdx.x * 256 + threadIdx.x;
    const double PI = 3.14159265358979323846;
    if (idx < 4096) {
        int n = idx / 64, x = idx % 64;
        double wn = PI * n / 64.0, wm = PI * x / 64.0;
        g_ldec[idx] = (float)(-(wn*wn + wm*wm));
    }
    if (idx < 2048) {
        int h = idx >> 6, pj = idx & 63;     // h < 32
        int p = pj >> 5, j = pj & 31;
        int n = 2*j + p;
        double v = cos((double)n * PI * ((double)h + 0.5) / 64.0) * sqrt(2.0 / 64.0);
        if (n == 0) v *= 0.70710678118654752440;
        g_WbfT[h*64 + pj] = (float)v;
        g_WbfJ[p*1024 + j*32 + h] = (float)v;
    }
}

// ---------------- fp32 -> fp16 conversion (vectorized) ----------------
__global__ __launch_bounds__(256) void tohalf4_kernel(
    const float* __restrict__ in, __half* __restrict__ out)
{
    long i = ((long)blockIdx.x*256 + threadIdx.x)*4;
    float4 v = *(const float4*)(in + i);
    __half2 h01 = __floats2half2_rn(v.x, v.y);
    __half2 h23 = __floats2half2_rn(v.z, v.w);
    uint2 pk;
    pk.x = *(uint32_t*)&h01;
    pk.y = *(uint32_t*)&h23;
    *(uint2*)(out + i) = pk;
}

// ---------------- K1: depthwise 3x3 conv, NCHW -> BHWC (fp16 out) ----
__global__ __launch_bounds__(256) void conv_kernel(
    const float* __restrict__ x, const float* __restrict__ w, const float* __restrict__ b)
{
    __shared__ float tile[64][65];
    int bh = blockIdx.x;
    int bb = bh >> 6, h = bh & 63;
    int tid = threadIdx.x;
    for (int cc = 0; cc < 6; cc++) {
        int c0 = cc * 64;
        #pragma unroll 4
        for (int it = 0; it < 16; it++) {
            int e = it * 256 + tid;
            int cl = e >> 6, ww = e & 63;
            int c = c0 + cl;
            const float* xp = x + ((long)(bb*CC + c) * HH) * WW;
            const float* wp = w + c * 9;
            float acc = b[c];
            #pragma unroll
            for (int dy = 0; dy < 3; dy++) {
                int hh = h + dy - 1;
                if (hh < 0 || hh >= 64) continue;
                #pragma unroll
                for (int dx = 0; dx < 3; dx++) {
                    int wx = ww + dx - 1;
                    if (wx < 0 || wx >= 64) continue;
                    acc += xp[hh*64 + wx] * wp[dy*3 + dx];
                }
            }
            tile[cl][ww] = acc;
        }
        __syncthreads();
        #pragma unroll 4
        for (int it = 0; it < 16; it++) {
            int e = it * 256 + tid;
            int ww = e >> 6, cl = e & 63;
            g_H1[(long)(bh*64 + ww) * CC + c0 + cl] = __float2half_rn(tile[cl][ww]);
        }
        __syncthreads();
    }
}

// ---------------- fp16 TC GEMM, 4-stage cp.async + ldmatrix ------------------
// EPI 0: plain+bias  EPI 1: gelu+modulation  EPI 2: plain+bias
// EPI 3: split — n0<384 -> fp32 to C (ldc=384); n0>=384 -> fp16 to Cz (col-384)
#define LDH 40
#define STGH (2*128*LDH)
#define GEMM_SMEM (4*STGH*2)
template<int EPI>
__global__ __launch_bounds__(256, 2) void gemm_fp16(
    const __half* __restrict__ A, const __half* __restrict__ Wt,
    const float* __restrict__ bias, float* __restrict__ C,
    int K, int ldc, const float* __restrict__ cptr, const float* __restrict__ aptr,
    __half* __restrict__ Cz)
{
    extern __shared__ __align__(16) __half hsm[];
    int tid = threadIdx.x;
    int m0 = blockIdx.y * 128;
    int n0 = blockIdx.x * 128;

    int rA0 = (tid      ) >> 2, cA0 = (tid      ) & 3;
    int rA1 = (tid + 256) >> 2, cA1 = (tid + 256) & 3;
    const __half* Ag0 = A  + (long)(m0 + rA0) * K + cA0*8;
    const __half* Ag1 = A  + (long)(m0 + rA1) * K + cA1*8;
    const __half* Bg0 = Wt + (long)(n0 + rA0) * K + cA0*8;
    const __half* Bg1 = Wt + (long)(n0 + rA1) * K + cA1*8;
    int sA0 = rA0*LDH + cA0*8;
    int sA1 = rA1*LDH + cA1*8;

    int warp = tid >> 5, lane = tid & 31;
    int g = lane >> 2, tig = lane & 3;
    int wm = warp & 3, wn = warp >> 2;

    int lrow = lane & 15;
    int lcol = (lane >> 4) * 8;
    uint32_t smem_base = (uint32_t)__cvta_generic_to_shared(hsm);

    float acc[2][8][4];
    #pragma unroll
    for (int i = 0; i < 2; i++)
        #pragma unroll
        for (int j = 0; j < 8; j++)
            #pragma unroll
            for (int q = 0; q < 4; q++) acc[i][j][q] = 0.f;

    int NK = K >> 5;

    #pragma unroll
    for (int s = 0; s < 3; s++) {
        __half* As = hsm + s*STGH;
        __half* Bs = As + 128*LDH;
        cpa16(As + sA0, Ag0 + s*32);
        cpa16(As + sA1, Ag1 + s*32);
        cpa16(Bs + sA0, Bg0 + s*32);
        cpa16(Bs + sA1, Bg1 + s*32);
        asm volatile("cp.async.commit_group;\n" ::);
    }

    for (int kt = 0; kt < NK; kt++) {
        asm volatile("cp.async.wait_group 2;\n" ::);
        __syncthreads();
        if (kt + 3 < NK) {
            int s = (kt + 3) & 3;
            __half* As = hsm + s*STGH;
            __half* Bs = As + 128*LDH;
            cpa16(As + sA0, Ag0 + (kt+3)*32);
            cpa16(As + sA1, Ag1 + (kt+3)*32);
            cpa16(Bs + sA0, Bg0 + (kt+3)*32);
            cpa16(Bs + sA1, Bg1 + (kt+3)*32);
        }
        asm volatile("cp.async.commit_group;\n" ::);

        uint32_t aBase = smem_base + (uint32_t)(((kt & 3)*STGH)            * 2);
        uint32_t bBase = smem_base + (uint32_t)(((kt & 3)*STGH + 128*LDH) * 2);
        #pragma unroll
        for (int ks = 0; ks < 32; ks += 16) {
            uint32_t af[2][4];
            #pragma unroll
            for (int mt = 0; mt < 2; mt++) {
                uint32_t addr = aBase + (uint32_t)(((wm*32 + mt*16 + lrow)*LDH + ks + lcol) * 2);
                ldsm_x4(af[mt][0], af[mt][1], af[mt][2], af[mt][3], addr);
            }
            uint32_t bf[8][2];
            #pragma unroll
            for (int pr = 0; pr < 4; pr++) {
                uint32_t addr = bBase + (uint32_t)(((wn*64 + pr*16 + lrow)*LDH + ks + lcol) * 2);
                uint32_t r0, r1, r2, r3;
                ldsm_x4(r0, r1, r2, r3, addr);
                bf[2*pr][0] = r0; bf[2*pr+1][0] = r1;
                bf[2*pr][1] = r2; bf[2*pr+1][1] = r3;
            }
            #pragma unroll
            for (int mt = 0; mt < 2; mt++)
                #pragma unroll
                for (int nt = 0; nt < 8; nt++)
                    mma_fp16(acc[mt][nt], af[mt], bf[nt]);
        }
    }

    float cv = 0.f, s1 = 0.f;
    if (EPI == 1) {
        cv = cptr[0];
        float al = aptr[0];
        s1 = (1.0f + 0.5f * al) / (cv + 1e-8f);
    }
    bool zblk = (EPI == 3) && (n0 >= 384);

    #pragma unroll
    for (int mt = 0; mt < 2; mt++) {
        int r0 = m0 + wm*32 + mt*16 + g;
        int r1 = r0 + 8;
        float ld0 = 0.f, ld1 = 0.f;
        if (EPI == 1) { ld0 = g_ldec[r0 & 4095]; ld1 = g_ldec[r1 & 4095]; }
        #pragma unroll
        for (int nt = 0; nt < 8; nt++) {
            int col = n0 + wn*64 + nt*8 + tig*2;
            float bsv0 = bias[col], bsv1 = bias[col+1];
            float v00 = acc[mt][nt][0] + bsv0;
            float v01 = acc[mt][nt][1] + bsv1;
            float v10 = acc[mt][nt][2] + bsv0;
            float v11 = acc[mt][nt][3] + bsv1;
            if (EPI == 1) {
                float t, ct;
                t  = 0.5f*v00*(1.0f + erff(v00*0.70710678f)); ct = cv*t;
                v00 = (__cosf(ct) + s1*__sinf(ct)) * __expf(t*ld0);
                t  = 0.5f*v01*(1.0f + erff(v01*0.70710678f)); ct = cv*t;
                v01 = (__cosf(ct) + s1*__sinf(ct)) * __expf(t*ld0);
                t  = 0.5f*v10*(1.0f + erff(v10*0.70710678f)); ct = cv*t;
                v10 = (__cosf(ct) + s1*__sinf(ct)) * __expf(t*ld1);
                t  = 0.5f*v11*(1.0f + erff(v11*0.70710678f)); ct = cv*t;
                v11 = (__cosf(ct) + s1*__sinf(ct)) * __expf(t*ld1);
            }
            if (zblk) {
                int zc = col - 384;
                *(__half2*)&Cz[(long)r0*384 + zc] = __floats2half2_rn(v00, v01);
                *(__half2*)&Cz[(long)r1*384 + zc] = __floats2half2_rn(v10, v11);
            } else {
                *(float2*)&C[(long)r0 * ldc + col] = make_float2(v00, v01);
                *(float2*)&C[(long)r1 * ldc + col] = make_float2(v10, v11);
            }
        }
    }
}

// ---------------- K4': forward DCT along H with input butterfly --------------
__global__ __launch_bounds__(256) void dct_h_fwd(
    const float* __restrict__ in, float* __restrict__ out, int ldin)
{
    __shared__ float Wt_s[32][64];
    __shared__ float tile[64][132];
    int w = blockIdx.x, bb = blockIdx.y;
    int tid = threadIdx.x;
    for (int i = tid; i < 2048; i += 256) Wt_s[i>>6][i&63] = g_WbfT[i];
    int tn = tid >> 5;
    int tc = tid & 31;
    int p  = tn & 1;
    int jb = (tn >> 1) * 8;
    const float* bin = in  + (long)(bb*4096 + w) * ldin;
    float*       bout = out + (long)(bb*4096 + w) * 384;
    for (int cc = 0; cc < 3; cc++) {
        int c0 = cc*128;
        #pragma unroll 4
        for (int it = 0; it < 32; it++) {
            int e = it*256 + tid;
            int r = e >> 7, cl = e & 127;
            tile[r][cl] = bin[(long)r*64*ldin + c0 + cl];
        }
        __syncthreads();
        #pragma unroll 4
        for (int it = 0; it < 16; it++) {
            int e = it*256 + tid;
            int h = e >> 7, cl = e & 127;
            float a = tile[h][cl], d = tile[63-h][cl];
            tile[h][cl]    = a + d;
            tile[63-h][cl] = a - d;
        }
        __syncthreads();
        float acc[8][4];
        #pragma unroll
        for (int i = 0; i < 8; i++)
            #pragma unroll
            for (int q = 0; q < 4; q++) acc[i][q] = 0.f;
        #pragma unroll 4
        for (int h = 0; h < 32; h++) {
            float wv[8], xv[4];
            *(float4*)wv     = *(const float4*)&Wt_s[h][p*32 + jb];
            *(float4*)(wv+4) = *(const float4*)&Wt_s[h][p*32 + jb + 4];
            int xr = p ? (63-h) : h;
            *(float4*)xv = *(const float4*)&tile[xr][tc*4];
            #pragma unroll
            for (int i = 0; i < 8; i++)
                #pragma unroll
                for (int q = 0; q < 4; q++)
                    acc[i][q] += wv[i]*xv[q];
        }
        #pragma unroll
        for (int i = 0; i < 8; i++) {
            int n = 2*(jb + i) + p;
            *(float4*)&bout[(long)n*64*384 + c0 + tc*4] =
                make_float4(acc[i][0], acc[i][1], acc[i][2], acc[i][3]);
        }
        __syncthreads();
    }
}

// ---------------- K5': DCT-W -> modulate(M) -> IDCT-W, butterfly, per (b,n) --
__global__ __launch_bounds__(256) void dctw_mod_bf(
    const float* __restrict__ in, float* __restrict__ out)
{
    __shared__ float Wt_s[32][64];
    __shared__ float We_s[32][36];
    __shared__ float Wo_s[32][36];
    __shared__ float tile[64][132];
    int nn = blockIdx.x, bb = blockIdx.y;
    int tid = threadIdx.x;
    for (int i = tid; i < 2048; i += 256) Wt_s[i>>6][i&63] = g_WbfT[i];
    for (int i = tid; i < 1024; i += 256) {
        We_s[i>>5][i&31] = g_WbfJ[i];
        Wo_s[i>>5][i&31] = g_WbfJ[1024 + i];
    }
    int tn = tid >> 5;
    int tc = tid & 31;
    int p  = tn & 1;
    int jb = (tn >> 1) * 8;
    int hb = tn*4;
    long base = (long)(bb*64 + nn) * 64 * 384;
    for (int cc = 0; cc < 3; cc++) {
        int c0 = cc*128;
        #pragma unroll 4
        for (int it = 0; it < 32; it++) {
            int e = it*256 + tid;
            int r = e >> 7, cl = e & 127;
            tile[r][cl] = in[base + (long)r*384 + c0 + cl];
        }
        __syncthreads();
        #pragma unroll 4
        for (int it = 0; it < 16; it++) {
            int e = it*256 + tid;
            int h = e >> 7, cl = e & 127;
            float a = tile[h][cl], d = tile[63-h][cl];
            tile[h][cl]    = a + d;
            tile[63-h][cl] = a - d;
        }
        __syncthreads();
        float acc[8][4];
        #pragma unroll
        for (int i = 0; i < 8; i++)
            #pragma unroll
            for (int q = 0; q < 4; q++) acc[i][q] = 0.f;
        #pragma unroll 4
        for (int h = 0; h < 32; h++) {
            float wv[8], xv[4];
            *(float4*)wv     = *(const float4*)&Wt_s[h][p*32 + jb];
            *(float4*)(wv+4) = *(const float4*)&Wt_s[h][p*32 + jb + 4];
            int xr = p ? (63-h) : h;
            *(float4*)xv = *(const float4*)&tile[xr][tc*4];
            #pragma unroll
            for (int i = 0; i < 8; i++)
                #pragma unroll
                for (int q = 0; q < 4; q++)
                    acc[i][q] += wv[i]*xv[q];
        }
        __syncthreads();
        #pragma unroll
        for (int i = 0; i < 8; i++) {
            int m = 2*(jb + i) + p;
            float4 mv = *(const float4*)&g_M[base + (long)m*384 + c0 + tc*4];
            *(float4*)&tile[m][tc*4] = make_float4(
                acc[i][0]*mv.x, acc[i][1]*mv.y, acc[i][2]*mv.z, acc[i][3]*mv.w);
        }
        __syncthreads();
        float accE[4][4], accO[4][4];
        #pragma unroll
        for (int i = 0; i < 4; i++)
            #pragma unroll
            for (int q = 0; q < 4; q++) { accE[i][q] = 0.f; accO[i][q] = 0.f; }
        #pragma unroll 4
        for (int j = 0; j < 32; j++) {
            float we[4], wo[4], ae[4], ao[4];
            *(float4*)we = *(const float4*)&We_s[j][hb];
            *(float4*)wo = *(const float4*)&Wo_s[j][hb];
            *(float4*)ae = *(const float4*)&tile[2*j][tc*4];
            *(float4*)ao = *(const float4*)&tile[2*j+1][tc*4];
            #pragma unroll
            for (int i = 0; i < 4; i++)
                #pragma unroll
                for (int q = 0; q < 4; q++) {
                    accE[i][q] += we[i]*ae[q];
                    accO[i][q] += wo[i]*ao[q];
                }
        }
        #pragma unroll
        for (int i = 0; i < 4; i++) {
            int h = hb + i;
            float4 vs = make_float4(accE[i][0]+accO[i][0], accE[i][1]+accO[i][1],
                                    accE[i][2]+accO[i][2], accE[i][3]+accO[i][3]);
            float4 vd = make_float4(accE[i][0]-accO[i][0], accE[i][1]-accO[i][1],
                                    accE[i][2]-accO[i][2], accE[i][3]-accO[i][3]);
            *(float4*)&out[base + (long)h*384 + c0 + tc*4] = vs;
            *(float4*)&out[base + (long)(63-h)*384 + c0 + tc*4] = vd;
        }
        __syncthreads();
    }
}

// ---------------- K6+7 fused: IDCT-H (butterfly) + LayerNorm + silu -> fp16 --
// smem: ybuf 64x388 + tile 64x132 + We/Wo + g/b
#define FUSE_SMEM ((64*388 + 64*132 + 2*32*36 + 2*384) * 4)
__global__ __launch_bounds__(256) void idct_ln_kernel(
    const float* __restrict__ in, const float* __restrict__ g, const float* __restrict__ bln)
{
    extern __shared__ __align__(16) float fsm[];
    float* ybuf = fsm;                    // 64*388
    float* tile = ybuf + 64*388;          // 64*132
    float* We_s = tile + 64*132;          // 32*36
    float* Wo_s = We_s + 32*36;           // 32*36
    float* gs   = Wo_s + 32*36;           // 384
    float* bs   = gs + 384;               // 384

    int w = blockIdx.x, bb = blockIdx.y;
    int tid = threadIdx.x;
    for (int i = tid; i < 1024; i += 256) {
        We_s[(i>>5)*36 + (i&31)] = g_WbfJ[i];
        Wo_s[(i>>5)*36 + (i&31)] = g_WbfJ[1024 + i];
    }
    for (int i = tid; i < 384; i += 256) { gs[i] = g[i]; bs[i] = bln[i]; }

    int tn = tid >> 5;        // warp 0..7
    int tc = tid & 31;
    int hb = tn*4;
    const float* bin = in + (long)(bb*4096 + w) * 384;

    for (int cc = 0; cc < 3; cc++) {
        int c0 = cc*128;
        #pragma unroll 4
        for (int it = 0; it < 32; it++) {
            int e = it*256 + tid;
            int r = e >> 7, cl = e & 127;
            tile[r*132 + cl] = bin[(long)r*64*384 + c0 + cl];
        }
        __syncthreads();
        float accE[4][4], accO[4][4];
        #pragma unroll
        for (int i = 0; i < 4; i++)
            #pragma unroll
            for (int q = 0; q < 4; q++) { accE[i][q] = 0.f; accO[i][q] = 0.f; }
        #pragma unroll 4
        for (int j = 0; j < 32; j++) {
            float we[4], wo[4], ae[4], ao[4];
            *(float4*)we = *(const float4*)&We_s[j*36 + hb];
            *(float4*)wo = *(const float4*)&Wo_s[j*36 + hb];
            *(float4*)ae = *(const float4*)&tile[(2*j)*132 + tc*4];
            *(float4*)ao = *(const float4*)&tile[(2*j+1)*132 + tc*4];
            #pragma unroll
            for (int i = 0; i < 4; i++)
                #pragma unroll
                for (int q = 0; q < 4; q++) {
                    accE[i][q] += we[i]*ae[q];
                    accO[i][q] += wo[i]*ao[q];
                }
        }
        #pragma unroll
        for (int i = 0; i < 4; i++) {
            int h = hb + i;
            *(float4*)&ybuf[h*388 + c0 + tc*4] = make_float4(
                accE[i][0]+accO[i][0], accE[i][1]+accO[i][1],
                accE[i][2]+accO[i][2], accE[i][3]+accO[i][3]);
            *(float4*)&ybuf[(63-h)*388 + c0 + tc*4] = make_float4(
                accE[i][0]-accO[i][0], accE[i][1]-accO[i][1],
                accE[i][2]-accO[i][2], accE[i][3]-accO[i][3]);
        }
        __syncthreads();
    }

    // LayerNorm + silu(z): warp tn handles rows tn*8 .. tn*8+7
    #pragma unroll 1
    for (int rr = 0; rr < 8; rr++) {
        int r = tn*8 + rr;
        float v[12];
        float s = 0.f, ss = 0.f;
        #pragma unroll
        for (int k = 0; k < 3; k++) {
            float4 q = *(const float4*)&ybuf[r*388 + k*128 + tc*4];
            v[k*4+0] = q.x; v[k*4+1] = q.y; v[k*4+2] = q.z; v[k*4+3] = q.w;
            s += q.x + q.y + q.z + q.w;
            ss += q.x*q.x + q.y*q.y + q.z*q.z + q.w*q.w;
        }
        #pragma unroll
        for (int o = 16; o; o >>= 1) {
            s  += __shfl_xor_sync(0xffffffffu, s,  o);
            ss += __shfl_xor_sync(0xffffffffu, ss, o);
        }
        float mu = s * (1.0f/384.0f);
        float var = ss * (1.0f/384.0f) - mu*mu;
        float rstd = rsqrtf(var + 1e-5f);
        long tok = (long)bb*4096 + r*64 + w;
        const __half* zp = g_Hz + tok*384;
        __half* op = g_H1 + tok*384;
        #pragma unroll
        for (int k = 0; k < 3; k++) {
            int c = k*128 + tc*4;
            float2 zf0 = __half22float2(*(const __half2*)&zp[c]);
            float2 zf1 = __half22float2(*(const __half2*)&zp[c+2]);
            float zv[4] = {zf0.x, zf0.y, zf1.x, zf1.y};
            __half hv[4];
            #pragma unroll
            for (int q = 0; q < 4; q++) {
                float val = (v[k*4+q] - mu)*rstd*gs[c+q] + bs[c+q];
                float z = zv[q];
                float si = z / (1.0f + __expf(-z));
                hv[q] = __float2half_rn(val * si);
            }
            *(__half2*)&op[c]   = __halves2half2(hv[0], hv[1]);
            *(__half2*)&op[c+2] = __halves2half2(hv[2], hv[3]);
        }
    }
}

// ---------------- launch ----------------
extern "C" void kernel_launch(void* const* d_in, const int* in_sizes, int n_in,
                              void* d_out, int out_size)
{
    (void)in_sizes; (void)n_in; (void)out_size;
    const float* x      = (const float*)d_in[0];
    const float* freq   = (const float*)d_in[1];
    const float* dw_w   = (const float*)d_in[2];
    const float* dw_b   = (const float*)d_in[3];
    const float* lin_w  = (const float*)d_in[4];
    const float* lin_b  = (const float*)d_in[5];
    const float* tok_w  = (const float*)d_in[6];
    const float* tok_b  = (const float*)d_in[7];
    const float* ln_g   = (const float*)d_in[8];
    const float* ln_b   = (const float*)d_in[9];
    const float* out_w  = (const float*)d_in[10];
    const float* out_b  = (const float*)d_in[11];
    const float* cp     = (const float*)d_in[12];
    const float* ap     = (const float*)d_in[13];
    float* out = (float*)d_out;

    void *pM_, *pX1_, *pA_, *pH1_, *pH2_, *pHz_, *pWH_;
    cudaGetSymbolAddress(&pM_,  g_M);
    cudaGetSymbolAddress(&pX1_, g_X1);
    cudaGetSymbolAddress(&pA_,  g_A);
    cudaGetSymbolAddress(&pH1_, g_H1);
    cudaGetSymbolAddress(&pH2_, g_H2);
    cudaGetSymbolAddress(&pHz_, g_Hz);
    cudaGetSymbolAddress(&pWH_, g_WH);
    float*  pM  = (float*)pM_;
    float*  pX1 = (float*)pX1_;
    float*  pA  = (float*)pA_;
    __half* pH1 = (__half*)pH1_;
    __half* pH2 = (__half*)pH2_;
    __half* pHz = (__half*)pHz_;
    __half* pWH = (__half*)pWH_;
    __half* h_lin = pWH;
    __half* h_tok = pWH + 768*384;
    __half* h_out = pWH + 768*384 + 384*384;

    cudaFuncSetAttribute(gemm_fp16<1>, cudaFuncAttributeMaxDynamicSharedMemorySize, GEMM_SMEM);
    cudaFuncSetAttribute(gemm_fp16<2>, cudaFuncAttributeMaxDynamicSharedMemorySize, GEMM_SMEM);
    cudaFuncSetAttribute(gemm_fp16<3>, cudaFuncAttributeMaxDynamicSharedMemorySize, GEMM_SMEM);
    cudaFuncSetAttribute(idct_ln_kernel, cudaFuncAttributeMaxDynamicSharedMemorySize, FUSE_SMEM);

    init_kernel<<<16, 256>>>();
    tohalf4_kernel<<<(768*384)/1024, 256>>>(lin_w, h_lin);
    tohalf4_kernel<<<(384*384)/1024, 256>>>(tok_w, h_tok);
    tohalf4_kernel<<<(384*384)/1024, 256>>>(out_w, h_out);
    tohalf4_kernel<<<((long)NT*CC)/1024, 256>>>(freq, pH2);
    // K1: dwconv -> g_H1 (BHWC, fp16)
    conv_kernel<<<BB*HH, 256>>>(x, dw_w, dw_b);
    // K2: split GEMM: xs -> g_X1 (fp32 [NT,384]); z -> g_Hz (fp16)
    gemm_fp16<3><<<dim3(6, 512), 256, GEMM_SMEM>>>(pH1, h_lin, lin_b, pX1, 384, 384, nullptr, nullptr, pHz);
    // K3: M = mod(gelu(freq @ tok_w^T + tok_b)) -> g_M
    gemm_fp16<1><<<dim3(3, 512), 256, GEMM_SMEM>>>(pH2, h_tok, tok_b, pM, 384, 384, cp, ap, nullptr);
    // K4': DCT-H (butterfly): g_X1 -> g_A
    dct_h_fwd<<<dim3(64, 16), 256>>>(pX1, pA, 384);
    // K5': DCT-W + modulate + IDCT-W (butterfly): g_A -> g_X1
    dctw_mod_bf<<<dim3(64, 16), 256>>>(pA, pX1);
    // K6+7: fused IDCT-H + LN + silu: g_X1 (+g_Hz) -> g_H1 (fp16)
    idct_ln_kernel<<<dim3(64, 16), 256, FUSE_SMEM>>>(pX1, ln_g, ln_b);
    // K8: out = ln_out @ out_w^T + out_b
    gemm_fp16<2><<<dim3(3, 512), 256, GEMM_SMEM>>>(pH1, h_out, out_b, out, 384, 384, nullptr, nullptr, nullptr);
}

// round 9
// speedup vs baseline: 1.1003x; 1.1003x over previous
#include <cuda_runtime.h>
#include <cuda_fp16.h>
#include <math.h>
#include <stdint.h>

#define BB 16
#define CC 384
#define HH 64
#define WW 64
#define NT (BB*HH*WW)   // 65536 tokens

// ---------------- scratch (static device globals; no allocs) ----------------
__device__ float  g_M [NT*CC];    // modulation (gemm2 out)
__device__ float  g_X1[NT*CC];    // xs (gemm1 out), then dctw out
__device__ float  g_A [NT*CC];    // DCT-H out / IDCT-H out
__device__ __half g_H1[NT*CC];    // conv out (gemm1 A), later ln out (gemm3 A)
__device__ __half g_H2[NT*CC];    // freq half (gemm2 A)
__device__ __half g_Hz[NT*CC];    // z (fp16)
__device__ __half g_WH[768*384 + 2*384*384];  // half weights
__device__ float  g_WbfT[32*64];  // [h][p*32+j] = W[2j+p][h], h<32
__device__ float  g_WbfJ[2*32*32];// [p][j][h]   = W[2j+p][h]
__device__ float  g_ldec[64*64];  // -(wn^2+wm^2) at (n,m)

// ---------------- helpers ----------------
__device__ __forceinline__ void cpa16(void* smem, const void* gmem) {
    unsigned s = (unsigned)__cvta_generic_to_shared(smem);
    asm volatile("cp.async.cg.shared.global [%0], [%1], 16;\n" :: "r"(s), "l"(gmem));
}

__device__ __forceinline__ void mma_fp16(float* d, const uint32_t* a, const uint32_t* b) {
    asm volatile(
        "mma.sync.aligned.m16n8k16.row.col.f32.f16.f16.f32 "
        "{%0,%1,%2,%3}, {%4,%5,%6,%7}, {%8,%9}, {%0,%1,%2,%3};\n"
        : "+f"(d[0]), "+f"(d[1]), "+f"(d[2]), "+f"(d[3])
        : "r"(a[0]), "r"(a[1]), "r"(a[2]), "r"(a[3]), "r"(b[0]), "r"(b[1]));
}

__device__ __forceinline__ void ldsm_x4(uint32_t& r0, uint32_t& r1, uint32_t& r2, uint32_t& r3,
                                        uint32_t addr) {
    asm volatile("ldmatrix.sync.aligned.m8n8.x4.shared.b16 {%0,%1,%2,%3}, [%4];"
                 : "=r"(r0), "=r"(r1), "=r"(r2), "=r"(r3) : "r"(addr));
}

// ---------------- init: packed butterfly DCT basis + decay log ----------------
__global__ void init_kernel() {
    int idx = blockIdx.x * 256 + threadIdx.x;
    const double PI = 3.14159265358979323846;
    if (idx < 4096) {
        int n = idx / 64, x = idx % 64;
        double wn = PI * n / 64.0, wm = PI * x / 64.0;
        g_ldec[idx] = (float)(-(wn*wn + wm*wm));
    }
    if (idx < 2048) {
        int h = idx >> 6, pj = idx & 63;     // h < 32
        int p = pj >> 5, j = pj & 31;
        int n = 2*j + p;
        double v = cos((double)n * PI * ((double)h + 0.5) / 64.0) * sqrt(2.0 / 64.0);
        if (n == 0) v *= 0.70710678118654752440;
        g_WbfT[h*64 + pj] = (float)v;
        g_WbfJ[p*1024 + j*32 + h] = (float)v;
    }
}

// ---------------- fp32 -> fp16 conversion (vectorized) ----------------
__global__ __launch_bounds__(256) void tohalf4_kernel(
    const float* __restrict__ in, __half* __restrict__ out)
{
    long i = ((long)blockIdx.x*256 + threadIdx.x)*4;
    float4 v = *(const float4*)(in + i);
    __half2 h01 = __floats2half2_rn(v.x, v.y);
    __half2 h23 = __floats2half2_rn(v.z, v.w);
    uint2 pk;
    pk.x = *(uint32_t*)&h01;
    pk.y = *(uint32_t*)&h23;
    *(uint2*)(out + i) = pk;
}

// ---------------- K1: depthwise 3x3 conv, NCHW -> BHWC (fp16 out) ----
__global__ __launch_bounds__(256) void conv_kernel(
    const float* __restrict__ x, const float* __restrict__ w, const float* __restrict__ b)
{
    __shared__ float tile[64][65];
    int bh = blockIdx.x;
    int bb = bh >> 6, h = bh & 63;
    int tid = threadIdx.x;
    for (int cc = 0; cc < 6; cc++) {
        int c0 = cc * 64;
        #pragma unroll 4
        for (int it = 0; it < 16; it++) {
            int e = it * 256 + tid;
            int cl = e >> 6, ww = e & 63;
            int c = c0 + cl;
            const float* xp = x + ((long)(bb*CC + c) * HH) * WW;
            const float* wp = w + c * 9;
            float acc = b[c];
            #pragma unroll
            for (int dy = 0; dy < 3; dy++) {
                int hh = h + dy - 1;
                if (hh < 0 || hh >= 64) continue;
                #pragma unroll
                for (int dx = 0; dx < 3; dx++) {
                    int wx = ww + dx - 1;
                    if (wx < 0 || wx >= 64) continue;
                    acc += xp[hh*64 + wx] * wp[dy*3 + dx];
                }
            }
            tile[cl][ww] = acc;
        }
        __syncthreads();
        #pragma unroll 4
        for (int it = 0; it < 16; it++) {
            int e = it * 256 + tid;
            int ww = e >> 6, cl = e & 63;
            g_H1[(long)(bh*64 + ww) * CC + c0 + cl] = __float2half_rn(tile[cl][ww]);
        }
        __syncthreads();
    }
}

// ---------------- fp16 TC GEMM, 4-stage cp.async + ldmatrix ------------------
// EPI 1: gelu+modulation  EPI 2: plain+bias
// EPI 3: split — n0<384 -> fp32 to C (ldc=384); n0>=384 -> fp16 to Cz (col-384)
#define LDH 40
#define STGH (2*128*LDH)
#define GEMM_SMEM (4*STGH*2)
template<int EPI>
__global__ __launch_bounds__(256, 2) void gemm_fp16(
    const __half* __restrict__ A, const __half* __restrict__ Wt,
    const float* __restrict__ bias, float* __restrict__ C,
    int K, int ldc, const float* __restrict__ cptr, const float* __restrict__ aptr,
    __half* __restrict__ Cz)
{
    extern __shared__ __align__(16) __half hsm[];
    int tid = threadIdx.x;
    int m0 = blockIdx.y * 128;
    int n0 = blockIdx.x * 128;

    int rA0 = (tid      ) >> 2, cA0 = (tid      ) & 3;
    int rA1 = (tid + 256) >> 2, cA1 = (tid + 256) & 3;
    const __half* Ag0 = A  + (long)(m0 + rA0) * K + cA0*8;
    const __half* Ag1 = A  + (long)(m0 + rA1) * K + cA1*8;
    const __half* Bg0 = Wt + (long)(n0 + rA0) * K + cA0*8;
    const __half* Bg1 = Wt + (long)(n0 + rA1) * K + cA1*8;
    int sA0 = rA0*LDH + cA0*8;
    int sA1 = rA1*LDH + cA1*8;

    int warp = tid >> 5, lane = tid & 31;
    int g = lane >> 2, tig = lane & 3;
    int wm = warp & 3, wn = warp >> 2;

    int lrow = lane & 15;
    int lcol = (lane >> 4) * 8;
    uint32_t smem_base = (uint32_t)__cvta_generic_to_shared(hsm);

    float acc[2][8][4];
    #pragma unroll
    for (int i = 0; i < 2; i++)
        #pragma unroll
        for (int j = 0; j < 8; j++)
            #pragma unroll
            for (int q = 0; q < 4; q++) acc[i][j][q] = 0.f;

    int NK = K >> 5;

    #pragma unroll
    for (int s = 0; s < 3; s++) {
        __half* As = hsm + s*STGH;
        __half* Bs = As + 128*LDH;
        cpa16(As + sA0, Ag0 + s*32);
        cpa16(As + sA1, Ag1 + s*32);
        cpa16(Bs + sA0, Bg0 + s*32);
        cpa16(Bs + sA1, Bg1 + s*32);
        asm volatile("cp.async.commit_group;\n" ::);
    }

    for (int kt = 0; kt < NK; kt++) {
        asm volatile("cp.async.wait_group 2;\n" ::);
        __syncthreads();
        if (kt + 3 < NK) {
            int s = (kt + 3) & 3;
            __half* As = hsm + s*STGH;
            __half* Bs = As + 128*LDH;
            cpa16(As + sA0, Ag0 + (kt+3)*32);
            cpa16(As + sA1, Ag1 + (kt+3)*32);
            cpa16(Bs + sA0, Bg0 + (kt+3)*32);
            cpa16(Bs + sA1, Bg1 + (kt+3)*32);
        }
        asm volatile("cp.async.commit_group;\n" ::);

        uint32_t aBase = smem_base + (uint32_t)(((kt & 3)*STGH)            * 2);
        uint32_t bBase = smem_base + (uint32_t)(((kt & 3)*STGH + 128*LDH) * 2);
        #pragma unroll
        for (int ks = 0; ks < 32; ks += 16) {
            uint32_t af[2][4];
            #pragma unroll
            for (int mt = 0; mt < 2; mt++) {
                uint32_t addr = aBase + (uint32_t)(((wm*32 + mt*16 + lrow)*LDH + ks + lcol) * 2);
                ldsm_x4(af[mt][0], af[mt][1], af[mt][2], af[mt][3], addr);
            }
            uint32_t bf[8][2];
            #pragma unroll
            for (int pr = 0; pr < 4; pr++) {
                uint32_t addr = bBase + (uint32_t)(((wn*64 + pr*16 + lrow)*LDH + ks + lcol) * 2);
                uint32_t r0, r1, r2, r3;
                ldsm_x4(r0, r1, r2, r3, addr);
                bf[2*pr][0] = r0; bf[2*pr+1][0] = r1;
                bf[2*pr][1] = r2; bf[2*pr+1][1] = r3;
            }
            #pragma unroll
            for (int mt = 0; mt < 2; mt++)
                #pragma unroll
                for (int nt = 0; nt < 8; nt++)
                    mma_fp16(acc[mt][nt], af[mt], bf[nt]);
        }
    }

    float cv = 0.f, s1 = 0.f;
    if (EPI == 1) {
        cv = cptr[0];
        float al = aptr[0];
        s1 = (1.0f + 0.5f * al) / (cv + 1e-8f);
    }
    bool zblk = (EPI == 3) && (n0 >= 384);

    #pragma unroll
    for (int mt = 0; mt < 2; mt++) {
        int r0 = m0 + wm*32 + mt*16 + g;
        int r1 = r0 + 8;
        float ld0 = 0.f, ld1 = 0.f;
        if (EPI == 1) { ld0 = g_ldec[r0 & 4095]; ld1 = g_ldec[r1 & 4095]; }
        #pragma unroll
        for (int nt = 0; nt < 8; nt++) {
            int col = n0 + wn*64 + nt*8 + tig*2;
            float bsv0 = bias[col], bsv1 = bias[col+1];
            float v00 = acc[mt][nt][0] + bsv0;
            float v01 = acc[mt][nt][1] + bsv1;
            float v10 = acc[mt][nt][2] + bsv0;
            float v11 = acc[mt][nt][3] + bsv1;
            if (EPI == 1) {
                float t, ct;
                t  = 0.5f*v00*(1.0f + erff(v00*0.70710678f)); ct = cv*t;
                v00 = (__cosf(ct) + s1*__sinf(ct)) * __expf(t*ld0);
                t  = 0.5f*v01*(1.0f + erff(v01*0.70710678f)); ct = cv*t;
                v01 = (__cosf(ct) + s1*__sinf(ct)) * __expf(t*ld0);
                t  = 0.5f*v10*(1.0f + erff(v10*0.70710678f)); ct = cv*t;
                v10 = (__cosf(ct) + s1*__sinf(ct)) * __expf(t*ld1);
                t  = 0.5f*v11*(1.0f + erff(v11*0.70710678f)); ct = cv*t;
                v11 = (__cosf(ct) + s1*__sinf(ct)) * __expf(t*ld1);
            }
            if (zblk) {
                int zc = col - 384;
                *(__half2*)&Cz[(long)r0*384 + zc] = __floats2half2_rn(v00, v01);
                *(__half2*)&Cz[(long)r1*384 + zc] = __floats2half2_rn(v10, v11);
            } else {
                *(float2*)&C[(long)r0 * ldc + col] = make_float2(v00, v01);
                *(float2*)&C[(long)r1 * ldc + col] = make_float2(v10, v11);
            }
        }
    }
}

// ---------------- K4': forward DCT along H with input butterfly --------------
__global__ __launch_bounds__(256) void dct_h_fwd(
    const float* __restrict__ in, float* __restrict__ out, int ldin)
{
    __shared__ float Wt_s[32][64];
    __shared__ float tile[64][132];
    int w = blockIdx.x, bb = blockIdx.y;
    int tid = threadIdx.x;
    for (int i = tid; i < 2048; i += 256) Wt_s[i>>6][i&63] = g_WbfT[i];
    int tn = tid >> 5;
    int tc = tid & 31;
    int p  = tn & 1;
    int jb = (tn >> 1) * 8;
    const float* bin = in  + (long)(bb*4096 + w) * ldin;
    float*       bout = out + (long)(bb*4096 + w) * 384;
    for (int cc = 0; cc < 3; cc++) {
        int c0 = cc*128;
        #pragma unroll 4
        for (int it = 0; it < 32; it++) {
            int e = it*256 + tid;
            int r = e >> 7, cl = e & 127;
            tile[r][cl] = bin[(long)r*64*ldin + c0 + cl];
        }
        __syncthreads();
        #pragma unroll 4
        for (int it = 0; it < 16; it++) {
            int e = it*256 + tid;
            int h = e >> 7, cl = e & 127;
            float a = tile[h][cl], d = tile[63-h][cl];
            tile[h][cl]    = a + d;
            tile[63-h][cl] = a - d;
        }
        __syncthreads();
        float acc[8][4];
        #pragma unroll
        for (int i = 0; i < 8; i++)
            #pragma unroll
            for (int q = 0; q < 4; q++) acc[i][q] = 0.f;
        #pragma unroll 4
        for (int h = 0; h < 32; h++) {
            float wv[8], xv[4];
            *(float4*)wv     = *(const float4*)&Wt_s[h][p*32 + jb];
            *(float4*)(wv+4) = *(const float4*)&Wt_s[h][p*32 + jb + 4];
            int xr = p ? (63-h) : h;
            *(float4*)xv = *(const float4*)&tile[xr][tc*4];
            #pragma unroll
            for (int i = 0; i < 8; i++)
                #pragma unroll
                for (int q = 0; q < 4; q++)
                    acc[i][q] += wv[i]*xv[q];
        }
        #pragma unroll
        for (int i = 0; i < 8; i++) {
            int n = 2*(jb + i) + p;
            *(float4*)&bout[(long)n*64*384 + c0 + tc*4] =
                make_float4(acc[i][0], acc[i][1], acc[i][2], acc[i][3]);
        }
        __syncthreads();
    }
}

// ---------------- K6': inverse DCT along H with output butterfly -------------
__global__ __launch_bounds__(256) void dct_h_inv(
    const float* __restrict__ in, float* __restrict__ out)
{
    __shared__ float We_s[32][36];
    __shared__ float Wo_s[32][36];
    __shared__ float tile[64][132];
    int w = blockIdx.x, bb = blockIdx.y;
    int tid = threadIdx.x;
    for (int i = tid; i < 1024; i += 256) {
        We_s[i>>5][i&31] = g_WbfJ[i];
        Wo_s[i>>5][i&31] = g_WbfJ[1024 + i];
    }
    int tn = tid >> 5;
    int tc = tid & 31;
    int hb = tn*4;
    const float* bin = in  + (long)(bb*4096 + w) * 384;
    float*       bout = out + (long)(bb*4096 + w) * 384;
    for (int cc = 0; cc < 3; cc++) {
        int c0 = cc*128;
        #pragma unroll 4
        for (int it = 0; it < 32; it++) {
            int e = it*256 + tid;
            int r = e >> 7, cl = e & 127;
            tile[r][cl] = bin[(long)r*64*384 + c0 + cl];
        }
        __syncthreads();
        float accE[4][4], accO[4][4];
        #pragma unroll
        for (int i = 0; i < 4; i++)
            #pragma unroll
            for (int q = 0; q < 4; q++) { accE[i][q] = 0.f; accO[i][q] = 0.f; }
        #pragma unroll 4
        for (int j = 0; j < 32; j++) {
            float we[4], wo[4], ae[4], ao[4];
            *(float4*)we = *(const float4*)&We_s[j][hb];
            *(float4*)wo = *(const float4*)&Wo_s[j][hb];
            *(float4*)ae = *(const float4*)&tile[2*j][tc*4];
            *(float4*)ao = *(const float4*)&tile[2*j+1][tc*4];
            #pragma unroll
            for (int i = 0; i < 4; i++)
                #pragma unroll
                for (int q = 0; q < 4; q++) {
                    accE[i][q] += we[i]*ae[q];
                    accO[i][q] += wo[i]*ao[q];
                }
        }
        #pragma unroll
        for (int i = 0; i < 4; i++) {
            int h = hb + i;
            float4 vs = make_float4(accE[i][0]+accO[i][0], accE[i][1]+accO[i][1],
                                    accE[i][2]+accO[i][2], accE[i][3]+accO[i][3]);
            float4 vd = make_float4(accE[i][0]-accO[i][0], accE[i][1]-accO[i][1],
                                    accE[i][2]-accO[i][2], accE[i][3]-accO[i][3]);
            *(float4*)&bout[(long)h*64*384 + c0 + tc*4] = vs;
            *(float4*)&bout[(long)(63-h)*64*384 + c0 + tc*4] = vd;
        }
        __syncthreads();
    }
}

// ---------------- K5': DCT-W -> modulate(M) -> IDCT-W, butterfly, per (b,n) --
__global__ __launch_bounds__(256) void dctw_mod_bf(
    const float* __restrict__ in, float* __restrict__ out)
{
    __shared__ float Wt_s[32][64];
    __shared__ float We_s[32][36];
    __shared__ float Wo_s[32][36];
    __shared__ float tile[64][132];
    int nn = blockIdx.x, bb = blockIdx.y;
    int tid = threadIdx.x;
    for (int i = tid; i < 2048; i += 256) Wt_s[i>>6][i&63] = g_WbfT[i];
    for (int i = tid; i < 1024; i += 256) {
        We_s[i>>5][i&31] = g_WbfJ[i];
        Wo_s[i>>5][i&31] = g_WbfJ[1024 + i];
    }
    int tn = tid >> 5;
    int tc = tid & 31;
    int p  = tn & 1;
    int jb = (tn >> 1) * 8;
    int hb = tn*4;
    long base = (long)(bb*64 + nn) * 64 * 384;
    for (int cc = 0; cc < 3; cc++) {
        int c0 = cc*128;
        #pragma unroll 4
        for (int it = 0; it < 32; it++) {
            int e = it*256 + tid;
            int r = e >> 7, cl = e & 127;
            tile[r][cl] = in[base + (long)r*384 + c0 + cl];
        }
        __syncthreads();
        #pragma unroll 4
        for (int it = 0; it < 16; it++) {
            int e = it*256 + tid;
            int h = e >> 7, cl = e & 127;
            float a = tile[h][cl], d = tile[63-h][cl];
            tile[h][cl]    = a + d;
            tile[63-h][cl] = a - d;
        }
        __syncthreads();
        float acc[8][4];
        #pragma unroll
        for (int i = 0; i < 8; i++)
            #pragma unroll
            for (int q = 0; q < 4; q++) acc[i][q] = 0.f;
        #pragma unroll 4
        for (int h = 0; h < 32; h++) {
            float wv[8], xv[4];
            *(float4*)wv     = *(const float4*)&Wt_s[h][p*32 + jb];
            *(float4*)(wv+4) = *(const float4*)&Wt_s[h][p*32 + jb + 4];
            int xr = p ? (63-h) : h;
            *(float4*)xv = *(const float4*)&tile[xr][tc*4];
            #pragma unroll
            for (int i = 0; i < 8; i++)
                #pragma unroll
                for (int q = 0; q < 4; q++)
                    acc[i][q] += wv[i]*xv[q];
        }
        __syncthreads();
        #pragma unroll
        for (int i = 0; i < 8; i++) {
            int m = 2*(jb + i) + p;
            float4 mv = *(const float4*)&g_M[base + (long)m*384 + c0 + tc*4];
            *(float4*)&tile[m][tc*4] = make_float4(
                acc[i][0]*mv.x, acc[i][1]*mv.y, acc[i][2]*mv.z, acc[i][3]*mv.w);
        }
        __syncthreads();
        float accE[4][4], accO[4][4];
        #pragma unroll
        for (int i = 0; i < 4; i++)
            #pragma unroll
            for (int q = 0; q < 4; q++) { accE[i][q] = 0.f; accO[i][q] = 0.f; }
        #pragma unroll 4
        for (int j = 0; j < 32; j++) {
            float we[4], wo[4], ae[4], ao[4];
            *(float4*)we = *(const float4*)&We_s[j][hb];
            *(float4*)wo = *(const float4*)&Wo_s[j][hb];
            *(float4*)ae = *(const float4*)&tile[2*j][tc*4];
            *(float4*)ao = *(const float4*)&tile[2*j+1][tc*4];
            #pragma unroll
            for (int i = 0; i < 4; i++)
                #pragma unroll
                for (int q = 0; q < 4; q++) {
                    accE[i][q] += we[i]*ae[q];
                    accO[i][q] += wo[i]*ao[q];
                }
        }
        #pragma unroll
        for (int i = 0; i < 4; i++) {
            int h = hb + i;
            float4 vs = make_float4(accE[i][0]+accO[i][0], accE[i][1]+accO[i][1],
                                    accE[i][2]+accO[i][2], accE[i][3]+accO[i][3]);
            float4 vd = make_float4(accE[i][0]-accO[i][0], accE[i][1]-accO[i][1],
                                    accE[i][2]-accO[i][2], accE[i][3]-accO[i][3]);
            *(float4*)&out[base + (long)h*384 + c0 + tc*4] = vs;
            *(float4*)&out[base + (long)(63-h)*384 + c0 + tc*4] = vd;
        }
        __syncthreads();
    }
}

// ---------------- K7: LayerNorm(C) * silu(z fp16) -> g_H1 (fp16) ------------
__global__ __launch_bounds__(128) void ln_silu_kernel(
    const float* __restrict__ xo, const float* __restrict__ g, const float* __restrict__ bln)
{
    int tok = blockIdx.x;
    int tid = threadIdx.x;
    const float* xp = xo + (long)tok * CC;
    float v[3], s = 0.f, ss = 0.f;
    #pragma unroll
    for (int k = 0; k < 3; k++) {
        v[k] = xp[tid + k*128];
        s += v[k]; ss += v[k]*v[k];
    }
    #pragma unroll
    for (int o = 16; o; o >>= 1) {
        s  += __shfl_xor_sync(0xffffffffu, s,  o);
        ss += __shfl_xor_sync(0xffffffffu, ss, o);
    }
    __shared__ float sh[8];
    int wid = tid >> 5, lid = tid & 31;
    if (lid == 0) { sh[wid] = s; sh[4 + wid] = ss; }
    __syncthreads();
    if (tid == 0) {
        float st  = sh[0]+sh[1]+sh[2]+sh[3];
        float sst = sh[4]+sh[5]+sh[6]+sh[7];
        sh[0] = st  * (1.0f/384.0f);
        sh[1] = sst * (1.0f/384.0f);
    }
    __syncthreads();
    float mu  = sh[0];
    float var = sh[1] - mu*mu;
    float rstd = rsqrtf(var + 1e-5f);
    const __half* zp = g_Hz + (long)tok*384;
    #pragma unroll
    for (int k = 0; k < 3; k++) {
        int c = tid + k*128;
        float val = (v[k] - mu) * rstd * g[c] + bln[c];
        float z = __half2float(zp[c]);
        float si = z / (1.0f + __expf(-z));
        g_H1[(long)tok*CC + c] = __float2half_rn(val * si);
    }
}

// ---------------- launch ----------------
extern "C" void kernel_launch(void* const* d_in, const int* in_sizes, int n_in,
                              void* d_out, int out_size)
{
    (void)in_sizes; (void)n_in; (void)out_size;
    const float* x      = (const float*)d_in[0];
    const float* freq   = (const float*)d_in[1];
    const float* dw_w   = (const float*)d_in[2];
    const float* dw_b   = (const float*)d_in[3];
    const float* lin_w  = (const float*)d_in[4];
    const float* lin_b  = (const float*)d_in[5];
    const float* tok_w  = (const float*)d_in[6];
    const float* tok_b  = (const float*)d_in[7];
    const float* ln_g   = (const float*)d_in[8];
    const float* ln_b   = (const float*)d_in[9];
    const float* out_w  = (const float*)d_in[10];
    const float* out_b  = (const float*)d_in[11];
    const float* cp     = (const float*)d_in[12];
    const float* ap     = (const float*)d_in[13];
    float* out = (float*)d_out;

    void *pM_, *pX1_, *pA_, *pH1_, *pH2_, *pHz_, *pWH_;
    cudaGetSymbolAddress(&pM_,  g_M);
    cudaGetSymbolAddress(&pX1_, g_X1);
    cudaGetSymbolAddress(&pA_,  g_A);
    cudaGetSymbolAddress(&pH1_, g_H1);
    cudaGetSymbolAddress(&pH2_, g_H2);
    cudaGetSymbolAddress(&pHz_, g_Hz);
    cudaGetSymbolAddress(&pWH_, g_WH);
    float*  pM  = (float*)pM_;
    float*  pX1 = (float*)pX1_;
    float*  pA  = (float*)pA_;
    __half* pH1 = (__half*)pH1_;
    __half* pH2 = (__half*)pH2_;
    __half* pHz = (__half*)pHz_;
    __half* pWH = (__half*)pWH_;
    __half* h_lin = pWH;
    __half* h_tok = pWH + 768*384;
    __half* h_out = pWH + 768*384 + 384*384;

    cudaFuncSetAttribute(gemm_fp16<1>, cudaFuncAttributeMaxDynamicSharedMemorySize, GEMM_SMEM);
    cudaFuncSetAttribute(gemm_fp16<2>, cudaFuncAttributeMaxDynamicSharedMemorySize, GEMM_SMEM);
    cudaFuncSetAttribute(gemm_fp16<3>, cudaFuncAttributeMaxDynamicSharedMemorySize, GEMM_SMEM);

    init_kernel<<<16, 256>>>();
    tohalf4_kernel<<<(768*384)/1024, 256>>>(lin_w, h_lin);
    tohalf4_kernel<<<(384*384)/1024, 256>>>(tok_w, h_tok);
    tohalf4_kernel<<<(384*384)/1024, 256>>>(out_w, h_out);
    tohalf4_kernel<<<((long)NT*CC)/1024, 256>>>(freq, pH2);
    // K1: dwconv -> g_H1 (BHWC, fp16)
    conv_kernel<<<BB*HH, 256>>>(x, dw_w, dw_b);
    // K2: split GEMM: xs -> g_X1 (fp32 [NT,384]); z -> g_Hz (fp16)
    gemm_fp16<3><<<dim3(6, 512), 256, GEMM_SMEM>>>(pH1, h_lin, lin_b, pX1, 384, 384, nullptr, nullptr, pHz);
    // K3: M = mod(gelu(freq @ tok_w^T + tok_b)) -> g_M
    gemm_fp16<1><<<dim3(3, 512), 256, GEMM_SMEM>>>(pH2, h_tok, tok_b, pM, 384, 384, cp, ap, nullptr);
    // K4': DCT-H (butterfly): g_X1 -> g_A
    dct_h_fwd<<<dim3(64, 16), 256>>>(pX1, pA, 384);
    // K5': DCT-W + modulate + IDCT-W (butterfly): g_A -> g_X1
    dctw_mod_bf<<<dim3(64, 16), 256>>>(pA, pX1);
    // K6': IDCT-H (butterfly): g_X1 -> g_A
    dct_h_inv<<<dim3(64, 16), 256>>>(pX1, pA);
    // K7: LN * silu(z fp16) -> g_H1 (fp16)
    ln_silu_kernel<<<NT, 128>>>(pA, ln_g, ln_b);
    // K8: out = ln_out @ out_w^T + out_b
    gemm_fp16<2><<<dim3(3, 512), 256, GEMM_SMEM>>>(pH1, h_out, out_b, out, 384, 384, nullptr, nullptr, nullptr);
}